// round 7
// baseline (speedup 1.0000x reference)
#include <cuda_runtime.h>
#include <cuda_fp16.h>
#include <math.h>

#define NNODES 100000
#define NEDGES 1600000
#define NEG 0.2f
#define GM_ROWS 128
#define CSR_BLOCKS 98

// ---------------- scratch (device globals; no allocation allowed) ----------
__device__ __half g_w1h[128 * 128];               // W1 fp16 transposed [n][k]
__device__ __half g_w2h[32 * 128];                // W2 fp16 transposed [n][k]
__device__ __half g_h1[NNODES * 128];             // layer1 features fp16
__device__ float  g_el1[NNODES * 4];
__device__ float  g_er1[NNODES * 4];
__device__ __half g_x2h[(NNODES + GM_ROWS) * 128];  // layer1 out (elu) fp16, padded
__device__ __half g_h2[NNODES * 32];              // layer2 features fp16
__device__ float  g_el2[NNODES];
__device__ float  g_er2[NNODES];
__device__ int    g_deg[NNODES];
__device__ int    g_rowptr[NNODES + 1];
__device__ int    g_cursor[NNODES];
__device__ int    g_csrc[NEDGES];
__device__ int    g_bsum[CSR_BLOCKS];
__device__ int    g_flags[128];   // [0..97] block flags, [98] sync1, [99] sync2

__device__ __forceinline__ unsigned packh2(float a, float b) {
    __half2 h = __floats2half2_rn(a, b);
    return *(unsigned*)&h;
}

// ---------------- setup: zero deg/flags, convert W1/W2 ----------------------
__global__ __launch_bounds__(256) void setup_kernel(const float* __restrict__ W1,
                                                    const float* __restrict__ W2) {
    int idx = blockIdx.x * 256 + threadIdx.x;
    int stride = gridDim.x * 256;
    for (int i = idx; i < 25000 + 32 + 16384 + 4096; i += stride) {
        if (i < 25000) {
            ((int4*)g_deg)[i] = make_int4(0, 0, 0, 0);
        } else if (i < 25032) {
            ((int4*)g_flags)[i - 25000] = make_int4(0, 0, 0, 0);
        } else if (i < 25032 + 16384) {
            int j = i - 25032;
            int k = j >> 7, n = j & 127;
            g_w1h[n * 128 + k] = __float2half_rn(W1[j]);
        } else {
            int j = i - 25032 - 16384;
            int k = j >> 5, n = j & 31;          // W2: [128][32]
            g_w2h[n * 128 + k] = __float2half_rn(W2[j]);
        }
    }
}

// ---------------- GEMM1 via HMMA: A direct from fp32 x ----------------------
// 256 threads (8 warps), 128 nodes/block; warp w -> rows w*16..w*16+15.
#define WS_STRIDE 136

__global__ __launch_bounds__(256) void gemm1_kernel(
    const float* __restrict__ x, const float* __restrict__ al,
    const float* __restrict__ ar) {
    __shared__ __half ws[128 * WS_STRIDE];  // 34.8 KB: ws[n][k] = W1^T
    int tid = threadIdx.x;
    int nb = blockIdx.x * GM_ROWS;

    for (int i = tid; i < 2048; i += 256) {
        int row = i >> 4, c = i & 15;
        *(uint4*)(ws + row * WS_STRIDE + c * 8) =
            *(const uint4*)(g_w1h + row * 128 + c * 8);
    }
    __syncthreads();

    int l = tid & 31, w = tid >> 5;
    int g4 = l >> 2, q = l & 3;
    int r0 = nb + w * 16 + g4;
    int r1 = r0 + 8;
    const float* xr0 = x + (size_t)(r0 < NNODES ? r0 : NNODES - 1) * 128;
    const float* xr1 = x + (size_t)(r1 < NNODES ? r1 : NNODES - 1) * 128;

    float d[16][4];
#pragma unroll
    for (int nt = 0; nt < 16; ++nt)
#pragma unroll
        for (int c = 0; c < 4; ++c) d[nt][c] = 0.f;

#pragma unroll
    for (int ks = 0; ks < 8; ++ks) {
        int kb = ks * 16 + q * 2;
        float2 f0 = *(const float2*)(xr0 + kb);
        float2 f1 = *(const float2*)(xr1 + kb);
        float2 f2 = *(const float2*)(xr0 + kb + 8);
        float2 f3 = *(const float2*)(xr1 + kb + 8);
        unsigned a0 = packh2(f0.x, f0.y);
        unsigned a1 = packh2(f1.x, f1.y);
        unsigned a2 = packh2(f2.x, f2.y);
        unsigned a3 = packh2(f3.x, f3.y);
#pragma unroll
        for (int nt = 0; nt < 16; ++nt) {
            const __half* wb = ws + (nt * 8 + g4) * WS_STRIDE + kb;
            unsigned b0 = *(const unsigned*)(wb);
            unsigned b1 = *(const unsigned*)(wb + 8);
            asm volatile(
                "mma.sync.aligned.m16n8k16.row.col.f32.f16.f16.f32 "
                "{%0,%1,%2,%3}, {%4,%5,%6,%7}, {%8,%9}, {%0,%1,%2,%3};"
                : "+f"(d[nt][0]), "+f"(d[nt][1]), "+f"(d[nt][2]), "+f"(d[nt][3])
                : "r"(a0), "r"(a1), "r"(a2), "r"(a3), "r"(b0), "r"(b1));
        }
    }

#pragma unroll
    for (int h = 0; h < 4; ++h) {
        float pel0 = 0.f, per0 = 0.f, pel1 = 0.f, per1 = 0.f;
#pragma unroll
        for (int t = 0; t < 4; ++t) {
            int nt = h * 4 + t;
            int c0 = nt * 8 + q * 2;
            float alv0 = __ldg(&al[c0]), alv1 = __ldg(&al[c0 + 1]);
            float arv0 = __ldg(&ar[c0]), arv1 = __ldg(&ar[c0 + 1]);
            pel0 += d[nt][0] * alv0 + d[nt][1] * alv1;
            per0 += d[nt][0] * arv0 + d[nt][1] * arv1;
            pel1 += d[nt][2] * alv0 + d[nt][3] * alv1;
            per1 += d[nt][2] * arv0 + d[nt][3] * arv1;
        }
#pragma unroll
        for (int o = 1; o < 4; o <<= 1) {
            pel0 += __shfl_xor_sync(0xffffffffu, pel0, o);
            per0 += __shfl_xor_sync(0xffffffffu, per0, o);
            pel1 += __shfl_xor_sync(0xffffffffu, pel1, o);
            per1 += __shfl_xor_sync(0xffffffffu, per1, o);
        }
        if (q == 0) {
            if (r0 < NNODES) { g_el1[r0 * 4 + h] = pel0; g_er1[r0 * 4 + h] = per0; }
            if (r1 < NNODES) { g_el1[r1 * 4 + h] = pel1; g_er1[r1 * 4 + h] = per1; }
        }
    }
#pragma unroll
    for (int nt = 0; nt < 16; ++nt) {
        int c0 = nt * 8 + q * 2;
        if (r0 < NNODES)
            ((__half2*)g_h1)[(size_t)r0 * 64 + (c0 >> 1)] =
                __floats2half2_rn(d[nt][0], d[nt][1]);
        if (r1 < NNODES)
            ((__half2*)g_h1)[(size_t)r1 * 64 + (c0 >> 1)] =
                __floats2half2_rn(d[nt][2], d[nt][3]);
    }
}

// ---------------- CSR build: count + scan + fill in ONE kernel --------------
// 98 blocks x 1024 threads, all resident (98 <= #SMs) -> spin grid-sync safe.
__global__ __launch_bounds__(1024) void csr_kernel(const int* __restrict__ src,
                                                   const int* __restrict__ dst) {
    __shared__ int s[1024];
    __shared__ int s_off;
    int b = blockIdx.x, tid = threadIdx.x;
    int gt = b * 1024 + tid;
    const int nthreads = CSR_BLOCKS * 1024;

    // phase 1: degree count (int4 over 400000 quads)
    for (int i = gt; i < NEDGES / 4; i += nthreads) {
        int4 d = ((const int4*)dst)[i];
        atomicAdd(&g_deg[d.x], 1);
        atomicAdd(&g_deg[d.y], 1);
        atomicAdd(&g_deg[d.z], 1);
        atomicAdd(&g_deg[d.w], 1);
    }
    __threadfence();
    __syncthreads();
    if (tid == 0) {
        atomicAdd(&g_flags[98], 1);
        while (atomicAdd(&g_flags[98], 0) < CSR_BLOCKS) {}
    }
    __syncthreads();

    // phase 2: scan (block b owns elements b*1024 .. +1023)
    int v = (gt < NNODES) ? g_deg[gt] : 0;
    s[tid] = v;
    __syncthreads();
    for (int off = 1; off < 1024; off <<= 1) {
        int t = (tid >= off) ? s[tid - off] : 0;
        __syncthreads();
        s[tid] += t;
        __syncthreads();
    }
    if (tid == 1023) {
        g_bsum[b] = s[1023];
        __threadfence();
        atomicExch(&g_flags[b], 1);
    }
    if (tid == 0) {
        int o = 0;
        for (int p = 0; p < b; ++p) {
            while (atomicAdd(&g_flags[p], 0) == 0) {}
            o += atomicAdd(&g_bsum[p], 0);
        }
        s_off = o;
    }
    __syncthreads();
    if (gt < NNODES) {
        int val = s_off + s[tid];
        g_rowptr[gt + 1] = val;
        if (gt + 1 < NNODES) g_cursor[gt + 1] = val;
    }
    if (gt == 0) { g_rowptr[0] = 0; g_cursor[0] = 0; }
    __threadfence();
    __syncthreads();
    if (tid == 0) {
        atomicAdd(&g_flags[99], 1);
        while (atomicAdd(&g_flags[99], 0) < CSR_BLOCKS) {}
    }
    __syncthreads();

    // phase 3: fill
    for (int i = gt; i < NEDGES / 4; i += nthreads) {
        int4 d = ((const int4*)dst)[i];
        int4 sc = ((const int4*)src)[i];
        g_csrc[atomicAdd(&g_cursor[d.x], 1)] = sc.x;
        g_csrc[atomicAdd(&g_cursor[d.y], 1)] = sc.y;
        g_csrc[atomicAdd(&g_cursor[d.z], 1)] = sc.z;
        g_csrc[atomicAdd(&g_cursor[d.w], 1)] = sc.w;
    }
}

// ---------------- AGG layer1: warp/node, 1-pass, depth-1 prefetch -----------
__global__ __launch_bounds__(256) void agg1_kernel(const float* __restrict__ b1) {
    int n = (blockIdx.x * 256 + threadIdx.x) >> 5;
    if (n >= NNODES) return;
    int l = threadIdx.x & 31;
    int h = l >> 3;
    int s0 = g_rowptr[n], s1 = g_rowptr[n + 1];
    float4 bv = ((const float4*)b1)[l];
    float4 res = bv;
    if (s1 > s0) {
        float ern = g_er1[n * 4 + h];
        float sm = 0.f;
        float4 acc = make_float4(0.f, 0.f, 0.f, 0.f);
        int s = g_csrc[s0];
        float els = __ldg(&g_el1[s * 4 + h]);
        for (int j = s0; j < s1; ++j) {
            int snext = (j + 1 < s1) ? g_csrc[j + 1] : 0;
            float elnext = __ldg(&g_el1[snext * 4 + h]);
            float e = els + ern;
            e = (e > 0.f) ? e : NEG * e;
            float wg = __expf(fminf(e, 60.f));
            uint2 p = ((const uint2*)g_h1)[(size_t)s * 32 + l];
            float2 f01 = __half22float2(*(__half2*)&p.x);
            float2 f23 = __half22float2(*(__half2*)&p.y);
            sm += wg;
            acc.x = fmaf(wg, f01.x, acc.x);
            acc.y = fmaf(wg, f01.y, acc.y);
            acc.z = fmaf(wg, f23.x, acc.z);
            acc.w = fmaf(wg, f23.y, acc.w);
            s = snext;
            els = elnext;
        }
        float inv = 1.f / sm;
        res = make_float4(fmaf(acc.x, inv, bv.x), fmaf(acc.y, inv, bv.y),
                          fmaf(acc.z, inv, bv.z), fmaf(acc.w, inv, bv.w));
    }
    // elu, then store fp16
    res.x = res.x > 0.f ? res.x : expm1f(res.x);
    res.y = res.y > 0.f ? res.y : expm1f(res.y);
    res.z = res.z > 0.f ? res.z : expm1f(res.z);
    res.w = res.w > 0.f ? res.w : expm1f(res.w);
    uint2 u;
    u.x = packh2(res.x, res.y);
    u.y = packh2(res.z, res.w);
    ((uint2*)g_x2h)[(size_t)n * 32 + l] = u;
}

// ---------------- GEMM2 via HMMA: h2 = x2 @ W2, fused el2/er2 ---------------
// mirror of gemm1 with 4 n-tiles (N=32), A from fp16 g_x2h (padded rows).
__global__ __launch_bounds__(256) void gemm2_kernel(
    const float* __restrict__ al, const float* __restrict__ ar) {
    __shared__ __half ws[32 * WS_STRIDE];  // 8.7 KB: ws[n][k] = W2^T
    int tid = threadIdx.x;
    int nb = blockIdx.x * GM_ROWS;

    for (int i = tid; i < 512; i += 256) {
        int row = i >> 4, c = i & 15;
        *(uint4*)(ws + row * WS_STRIDE + c * 8) =
            *(const uint4*)(g_w2h + row * 128 + c * 8);
    }
    __syncthreads();

    int l = tid & 31, w = tid >> 5;
    int g4 = l >> 2, q = l & 3;
    int r0 = nb + w * 16 + g4;
    int r1 = r0 + 8;
    const __half* xr0 = g_x2h + (size_t)r0 * 128;
    const __half* xr1 = g_x2h + (size_t)r1 * 128;

    float d[4][4];
#pragma unroll
    for (int nt = 0; nt < 4; ++nt)
#pragma unroll
        for (int c = 0; c < 4; ++c) d[nt][c] = 0.f;

#pragma unroll
    for (int ks = 0; ks < 8; ++ks) {
        int kb = ks * 16 + q * 2;
        unsigned a0 = *(const unsigned*)(xr0 + kb);
        unsigned a1 = *(const unsigned*)(xr1 + kb);
        unsigned a2 = *(const unsigned*)(xr0 + kb + 8);
        unsigned a3 = *(const unsigned*)(xr1 + kb + 8);
#pragma unroll
        for (int nt = 0; nt < 4; ++nt) {
            const __half* wb = ws + (nt * 8 + g4) * WS_STRIDE + kb;
            unsigned b0 = *(const unsigned*)(wb);
            unsigned b1 = *(const unsigned*)(wb + 8);
            asm volatile(
                "mma.sync.aligned.m16n8k16.row.col.f32.f16.f16.f32 "
                "{%0,%1,%2,%3}, {%4,%5,%6,%7}, {%8,%9}, {%0,%1,%2,%3};"
                : "+f"(d[nt][0]), "+f"(d[nt][1]), "+f"(d[nt][2]), "+f"(d[nt][3])
                : "r"(a0), "r"(a1), "r"(a2), "r"(a3), "r"(b0), "r"(b1));
        }
    }

    // fused attention dots (single head, 32 cols = 4 n-tiles)
    {
        float pel0 = 0.f, per0 = 0.f, pel1 = 0.f, per1 = 0.f;
#pragma unroll
        for (int nt = 0; nt < 4; ++nt) {
            int c0 = nt * 8 + q * 2;
            float alv0 = __ldg(&al[c0]), alv1 = __ldg(&al[c0 + 1]);
            float arv0 = __ldg(&ar[c0]), arv1 = __ldg(&ar[c0 + 1]);
            pel0 += d[nt][0] * alv0 + d[nt][1] * alv1;
            per0 += d[nt][0] * arv0 + d[nt][1] * arv1;
            pel1 += d[nt][2] * alv0 + d[nt][3] * alv1;
            per1 += d[nt][2] * arv0 + d[nt][3] * arv1;
        }
#pragma unroll
        for (int o = 1; o < 4; o <<= 1) {
            pel0 += __shfl_xor_sync(0xffffffffu, pel0, o);
            per0 += __shfl_xor_sync(0xffffffffu, per0, o);
            pel1 += __shfl_xor_sync(0xffffffffu, pel1, o);
            per1 += __shfl_xor_sync(0xffffffffu, per1, o);
        }
        if (q == 0) {
            if (r0 < NNODES) { g_el2[r0] = pel0; g_er2[r0] = per0; }
            if (r1 < NNODES) { g_el2[r1] = pel1; g_er2[r1] = per1; }
        }
    }
#pragma unroll
    for (int nt = 0; nt < 4; ++nt) {
        int c0 = nt * 8 + q * 2;
        if (r0 < NNODES)
            ((__half2*)g_h2)[(size_t)r0 * 16 + (c0 >> 1)] =
                __floats2half2_rn(d[nt][0], d[nt][1]);
        if (r1 < NNODES)
            ((__half2*)g_h2)[(size_t)r1 * 16 + (c0 >> 1)] =
                __floats2half2_rn(d[nt][2], d[nt][3]);
    }
}

// ---------------- AGG layer2: warp/node, 1-pass, depth-1 prefetch -----------
__global__ __launch_bounds__(256) void agg2_kernel(const float* __restrict__ b2,
                                                   float* __restrict__ out) {
    int n = (blockIdx.x * 256 + threadIdx.x) >> 5;
    if (n >= NNODES) return;
    int l = threadIdx.x & 31;
    int s0 = g_rowptr[n], s1 = g_rowptr[n + 1];
    float bv = b2[l];
    float val = bv;
    if (s1 > s0) {
        float ern = g_er2[n];
        float sm = 0.f, acc = 0.f;
        int s = g_csrc[s0];
        float els = __ldg(&g_el2[s]);
        for (int j = s0; j < s1; ++j) {
            int snext = (j + 1 < s1) ? g_csrc[j + 1] : 0;
            float elnext = __ldg(&g_el2[snext]);
            float e = els + ern;
            e = (e > 0.f) ? e : NEG * e;
            float wg = __expf(fminf(e, 60.f));
            float f = __half2float(g_h2[(size_t)s * 32 + l]);
            sm += wg;
            acc = fmaf(wg, f, acc);
            s = snext;
            els = elnext;
        }
        val = acc / sm + bv;
    }
    out[(size_t)n * 32 + l] = val;
}

// ---------------- launch ----------------------------------------------------
extern "C" void kernel_launch(void* const* d_in, const int* in_sizes, int n_in,
                              void* d_out, int out_size) {
    const float* x   = (const float*)d_in[0];
    const int*   src = (const int*)d_in[1];
    const int*   dst = (const int*)d_in[2];
    const float* W1  = (const float*)d_in[3];
    const float* al1 = (const float*)d_in[4];
    const float* ar1 = (const float*)d_in[5];
    const float* b1  = (const float*)d_in[6];
    const float* W2  = (const float*)d_in[7];
    const float* al2 = (const float*)d_in[8];
    const float* ar2 = (const float*)d_in[9];
    const float* b2  = (const float*)d_in[10];
    float* out = (float*)d_out;

    setup_kernel<<<64, 256>>>(W1, W2);
    gemm1_kernel<<<(NNODES + GM_ROWS - 1) / GM_ROWS, 256>>>(x, al1, ar1);
    csr_kernel<<<CSR_BLOCKS, 1024>>>(src, dst);
    agg1_kernel<<<(NNODES * 32 + 255) / 256, 256>>>(b1);   // launch idx 3: profiled
    gemm2_kernel<<<(NNODES + GM_ROWS - 1) / GM_ROWS, 256>>>(al2, ar2);
    agg2_kernel<<<(NNODES * 32 + 255) / 256, 256>>>(b2, out);
}

// round 8
// speedup vs baseline: 1.1540x; 1.1540x over previous
#include <cuda_runtime.h>
#include <cuda_fp16.h>
#include <math.h>

#define NNODES 100000
#define NEDGES 1600000
#define NEG 0.2f
#define GM_ROWS 128
#define CSR_BLOCKS 98

// ---------------- scratch (device globals; no allocation allowed) ----------
__device__ __half g_w1h[128 * 128];               // W1 fp16 transposed [n][k]
__device__ __half g_w2h[32 * 128];                // W2 fp16 transposed [n][k]
__device__ __half g_h1[NNODES * 128];             // layer1 features fp16
__device__ float  g_el1[NNODES * 4];
__device__ float  g_er1[NNODES * 4];
__device__ __half g_x2h[(NNODES + GM_ROWS) * 128];  // layer1 out (elu) fp16, padded
__device__ __half g_h2[NNODES * 32];              // layer2 features fp16
__device__ float  g_el2[NNODES];
__device__ float  g_er2[NNODES];
__device__ int    g_deg[NNODES];
__device__ int    g_rowptr[NNODES + 1];
__device__ int    g_cursor[NNODES];
__device__ int    g_csrc[NEDGES];
__device__ int    g_cdst[NEDGES];
__device__ float4 g_w1e[NEDGES];                  // layer1 edge weights (4 heads)
__device__ float  g_w2e[NEDGES];                  // layer2 edge weights
__device__ int    g_bsum[CSR_BLOCKS];
__device__ int    g_flags[128];   // [0..97] block flags, [98] sync1, [99] sync2

__device__ __forceinline__ unsigned packh2(float a, float b) {
    __half2 h = __floats2half2_rn(a, b);
    return *(unsigned*)&h;
}
__device__ __forceinline__ float edgew(float e) {
    e = (e > 0.f) ? e : NEG * e;
    return __expf(fminf(e, 60.f));
}

// ---------------- setup: zero deg/flags, convert W1/W2 ----------------------
__global__ __launch_bounds__(256) void setup_kernel(const float* __restrict__ W1,
                                                    const float* __restrict__ W2) {
    int idx = blockIdx.x * 256 + threadIdx.x;
    int stride = gridDim.x * 256;
    for (int i = idx; i < 25000 + 32 + 16384 + 4096; i += stride) {
        if (i < 25000) {
            ((int4*)g_deg)[i] = make_int4(0, 0, 0, 0);
        } else if (i < 25032) {
            ((int4*)g_flags)[i - 25000] = make_int4(0, 0, 0, 0);
        } else if (i < 25032 + 16384) {
            int j = i - 25032;
            int k = j >> 7, n = j & 127;
            g_w1h[n * 128 + k] = __float2half_rn(W1[j]);
        } else {
            int j = i - 25032 - 16384;
            int k = j >> 5, n = j & 31;          // W2: [128][32]
            g_w2h[n * 128 + k] = __float2half_rn(W2[j]);
        }
    }
}

// ---------------- GEMM1 via HMMA: A direct from fp32 x ----------------------
#define WS_STRIDE 136

__global__ __launch_bounds__(256) void gemm1_kernel(
    const float* __restrict__ x, const float* __restrict__ al,
    const float* __restrict__ ar) {
    __shared__ __half ws[128 * WS_STRIDE];  // 34.8 KB: ws[n][k] = W1^T
    int tid = threadIdx.x;
    int nb = blockIdx.x * GM_ROWS;

    for (int i = tid; i < 2048; i += 256) {
        int row = i >> 4, c = i & 15;
        *(uint4*)(ws + row * WS_STRIDE + c * 8) =
            *(const uint4*)(g_w1h + row * 128 + c * 8);
    }
    __syncthreads();

    int l = tid & 31, w = tid >> 5;
    int g4 = l >> 2, q = l & 3;
    int r0 = nb + w * 16 + g4;
    int r1 = r0 + 8;
    const float* xr0 = x + (size_t)(r0 < NNODES ? r0 : NNODES - 1) * 128;
    const float* xr1 = x + (size_t)(r1 < NNODES ? r1 : NNODES - 1) * 128;

    float d[16][4];
#pragma unroll
    for (int nt = 0; nt < 16; ++nt)
#pragma unroll
        for (int c = 0; c < 4; ++c) d[nt][c] = 0.f;

#pragma unroll
    for (int ks = 0; ks < 8; ++ks) {
        int kb = ks * 16 + q * 2;
        float2 f0 = *(const float2*)(xr0 + kb);
        float2 f1 = *(const float2*)(xr1 + kb);
        float2 f2 = *(const float2*)(xr0 + kb + 8);
        float2 f3 = *(const float2*)(xr1 + kb + 8);
        unsigned a0 = packh2(f0.x, f0.y);
        unsigned a1 = packh2(f1.x, f1.y);
        unsigned a2 = packh2(f2.x, f2.y);
        unsigned a3 = packh2(f3.x, f3.y);
#pragma unroll
        for (int nt = 0; nt < 16; ++nt) {
            const __half* wb = ws + (nt * 8 + g4) * WS_STRIDE + kb;
            unsigned b0 = *(const unsigned*)(wb);
            unsigned b1 = *(const unsigned*)(wb + 8);
            asm volatile(
                "mma.sync.aligned.m16n8k16.row.col.f32.f16.f16.f32 "
                "{%0,%1,%2,%3}, {%4,%5,%6,%7}, {%8,%9}, {%0,%1,%2,%3};"
                : "+f"(d[nt][0]), "+f"(d[nt][1]), "+f"(d[nt][2]), "+f"(d[nt][3])
                : "r"(a0), "r"(a1), "r"(a2), "r"(a3), "r"(b0), "r"(b1));
        }
    }

#pragma unroll
    for (int h = 0; h < 4; ++h) {
        float pel0 = 0.f, per0 = 0.f, pel1 = 0.f, per1 = 0.f;
#pragma unroll
        for (int t = 0; t < 4; ++t) {
            int nt = h * 4 + t;
            int c0 = nt * 8 + q * 2;
            float alv0 = __ldg(&al[c0]), alv1 = __ldg(&al[c0 + 1]);
            float arv0 = __ldg(&ar[c0]), arv1 = __ldg(&ar[c0 + 1]);
            pel0 += d[nt][0] * alv0 + d[nt][1] * alv1;
            per0 += d[nt][0] * arv0 + d[nt][1] * arv1;
            pel1 += d[nt][2] * alv0 + d[nt][3] * alv1;
            per1 += d[nt][2] * arv0 + d[nt][3] * arv1;
        }
#pragma unroll
        for (int o = 1; o < 4; o <<= 1) {
            pel0 += __shfl_xor_sync(0xffffffffu, pel0, o);
            per0 += __shfl_xor_sync(0xffffffffu, per0, o);
            pel1 += __shfl_xor_sync(0xffffffffu, pel1, o);
            per1 += __shfl_xor_sync(0xffffffffu, per1, o);
        }
        if (q == 0) {
            if (r0 < NNODES) { g_el1[r0 * 4 + h] = pel0; g_er1[r0 * 4 + h] = per0; }
            if (r1 < NNODES) { g_el1[r1 * 4 + h] = pel1; g_er1[r1 * 4 + h] = per1; }
        }
    }
#pragma unroll
    for (int nt = 0; nt < 16; ++nt) {
        int c0 = nt * 8 + q * 2;
        if (r0 < NNODES)
            ((__half2*)g_h1)[(size_t)r0 * 64 + (c0 >> 1)] =
                __floats2half2_rn(d[nt][0], d[nt][1]);
        if (r1 < NNODES)
            ((__half2*)g_h1)[(size_t)r1 * 64 + (c0 >> 1)] =
                __floats2half2_rn(d[nt][2], d[nt][3]);
    }
}

// ---------------- CSR build + layer1 edge weights, ONE kernel ---------------
// 98 blocks x 1024 threads, all resident -> spin grid-sync safe.
__global__ __launch_bounds__(1024) void csr_kernel(const int* __restrict__ src,
                                                   const int* __restrict__ dst) {
    __shared__ int s[1024];
    __shared__ int s_off;
    int b = blockIdx.x, tid = threadIdx.x;
    int gt = b * 1024 + tid;
    const int nthreads = CSR_BLOCKS * 1024;

    // phase 1: degree count
    for (int i = gt; i < NEDGES / 4; i += nthreads) {
        int4 d = ((const int4*)dst)[i];
        atomicAdd(&g_deg[d.x], 1);
        atomicAdd(&g_deg[d.y], 1);
        atomicAdd(&g_deg[d.z], 1);
        atomicAdd(&g_deg[d.w], 1);
    }
    __threadfence();
    __syncthreads();
    if (tid == 0) {
        atomicAdd(&g_flags[98], 1);
        while (atomicAdd(&g_flags[98], 0) < CSR_BLOCKS) {}
    }
    __syncthreads();

    // phase 2: scan (block b owns elements b*1024 .. +1023)
    int v = (gt < NNODES) ? g_deg[gt] : 0;
    s[tid] = v;
    if (tid == 0) s_off = 0;
    __syncthreads();
    for (int off = 1; off < 1024; off <<= 1) {
        int t = (tid >= off) ? s[tid - off] : 0;
        __syncthreads();
        s[tid] += t;
        __syncthreads();
    }
    if (tid == 1023) {
        g_bsum[b] = s[1023];
        __threadfence();
        atomicExch(&g_flags[b], 1);
    }
    // parallel lookback: thread p (< b) polls predecessor p
    if (tid < b) {
        while (atomicAdd(&g_flags[tid], 0) == 0) {}
        atomicAdd(&s_off, atomicAdd(&g_bsum[tid], 0));
    }
    __syncthreads();
    if (gt < NNODES) {
        int val = s_off + s[tid];
        g_rowptr[gt + 1] = val;
        if (gt + 1 < NNODES) g_cursor[gt + 1] = val;
    }
    if (gt == 0) { g_rowptr[0] = 0; g_cursor[0] = 0; }
    __threadfence();
    __syncthreads();
    if (tid == 0) {
        atomicAdd(&g_flags[99], 1);
        while (atomicAdd(&g_flags[99], 0) < CSR_BLOCKS) {}
    }
    __syncthreads();

    // phase 3: fill + layer1 edge weights (el1/er1 ready: gemm1 ran before)
    for (int i = gt; i < NEDGES / 4; i += nthreads) {
        int4 d4 = ((const int4*)dst)[i];
        int4 s4 = ((const int4*)src)[i];
        int dd[4] = {d4.x, d4.y, d4.z, d4.w};
        int ss[4] = {s4.x, s4.y, s4.z, s4.w};
#pragma unroll
        for (int e = 0; e < 4; ++e) {
            int d = dd[e], sc = ss[e];
            int p = atomicAdd(&g_cursor[d], 1);
            g_csrc[p] = sc;
            g_cdst[p] = d;
            float4 el = __ldg((const float4*)&g_el1[sc * 4]);
            float4 er = __ldg((const float4*)&g_er1[d * 4]);
            float4 w;
            w.x = edgew(el.x + er.x);
            w.y = edgew(el.y + er.y);
            w.z = edgew(el.z + er.z);
            w.w = edgew(el.w + er.w);
            g_w1e[p] = w;
        }
    }
}

// ---------------- layer2 edge weights (after gemm2) -------------------------
__global__ __launch_bounds__(256) void w2e_kernel() {
    int j = blockIdx.x * 256 + threadIdx.x;
    if (j < NEDGES) {
        int s = g_csrc[j], d = g_cdst[j];
        g_w2e[j] = edgew(__ldg(&g_el2[s]) + __ldg(&g_er2[d]));
    }
}

// ---------------- AGG layer1: warp/node, precomputed weights ----------------
__global__ __launch_bounds__(256) void agg1_kernel(const float* __restrict__ b1) {
    int n = (blockIdx.x * 256 + threadIdx.x) >> 5;
    if (n >= NNODES) return;
    int l = threadIdx.x & 31;
    int h = l >> 3;
    int s0 = g_rowptr[n], s1 = g_rowptr[n + 1];
    float4 bv = ((const float4*)b1)[l];
    float4 res = bv;
    if (s1 > s0) {
        float sm = 0.f;
        float4 acc = make_float4(0.f, 0.f, 0.f, 0.f);
        const float* wbase = (const float*)g_w1e;
        int s = g_csrc[s0];
        for (int j = s0; j < s1; ++j) {
            int snext = (j + 1 < s1) ? g_csrc[j + 1] : 0;
            float wg = __ldg(&wbase[(size_t)j * 4 + h]);
            uint2 p = ((const uint2*)g_h1)[(size_t)s * 32 + l];
            float2 f01 = __half22float2(*(__half2*)&p.x);
            float2 f23 = __half22float2(*(__half2*)&p.y);
            sm += wg;
            acc.x = fmaf(wg, f01.x, acc.x);
            acc.y = fmaf(wg, f01.y, acc.y);
            acc.z = fmaf(wg, f23.x, acc.z);
            acc.w = fmaf(wg, f23.y, acc.w);
            s = snext;
        }
        float inv = 1.f / sm;
        res = make_float4(fmaf(acc.x, inv, bv.x), fmaf(acc.y, inv, bv.y),
                          fmaf(acc.z, inv, bv.z), fmaf(acc.w, inv, bv.w));
    }
    res.x = res.x > 0.f ? res.x : expm1f(res.x);
    res.y = res.y > 0.f ? res.y : expm1f(res.y);
    res.z = res.z > 0.f ? res.z : expm1f(res.z);
    res.w = res.w > 0.f ? res.w : expm1f(res.w);
    uint2 u;
    u.x = packh2(res.x, res.y);
    u.y = packh2(res.z, res.w);
    ((uint2*)g_x2h)[(size_t)n * 32 + l] = u;
}

// ---------------- GEMM2 via HMMA: h2 = x2 @ W2, fused el2/er2 ---------------
__global__ __launch_bounds__(256) void gemm2_kernel(
    const float* __restrict__ al, const float* __restrict__ ar) {
    __shared__ __half ws[32 * WS_STRIDE];  // 8.7 KB: ws[n][k] = W2^T
    int tid = threadIdx.x;
    int nb = blockIdx.x * GM_ROWS;

    for (int i = tid; i < 512; i += 256) {
        int row = i >> 4, c = i & 15;
        *(uint4*)(ws + row * WS_STRIDE + c * 8) =
            *(const uint4*)(g_w2h + row * 128 + c * 8);
    }
    __syncthreads();

    int l = tid & 31, w = tid >> 5;
    int g4 = l >> 2, q = l & 3;
    int r0 = nb + w * 16 + g4;
    int r1 = r0 + 8;
    const __half* xr0 = g_x2h + (size_t)r0 * 128;
    const __half* xr1 = g_x2h + (size_t)r1 * 128;

    float d[4][4];
#pragma unroll
    for (int nt = 0; nt < 4; ++nt)
#pragma unroll
        for (int c = 0; c < 4; ++c) d[nt][c] = 0.f;

#pragma unroll
    for (int ks = 0; ks < 8; ++ks) {
        int kb = ks * 16 + q * 2;
        unsigned a0 = *(const unsigned*)(xr0 + kb);
        unsigned a1 = *(const unsigned*)(xr1 + kb);
        unsigned a2 = *(const unsigned*)(xr0 + kb + 8);
        unsigned a3 = *(const unsigned*)(xr1 + kb + 8);
#pragma unroll
        for (int nt = 0; nt < 4; ++nt) {
            const __half* wb = ws + (nt * 8 + g4) * WS_STRIDE + kb;
            unsigned b0 = *(const unsigned*)(wb);
            unsigned b1 = *(const unsigned*)(wb + 8);
            asm volatile(
                "mma.sync.aligned.m16n8k16.row.col.f32.f16.f16.f32 "
                "{%0,%1,%2,%3}, {%4,%5,%6,%7}, {%8,%9}, {%0,%1,%2,%3};"
                : "+f"(d[nt][0]), "+f"(d[nt][1]), "+f"(d[nt][2]), "+f"(d[nt][3])
                : "r"(a0), "r"(a1), "r"(a2), "r"(a3), "r"(b0), "r"(b1));
        }
    }

    {
        float pel0 = 0.f, per0 = 0.f, pel1 = 0.f, per1 = 0.f;
#pragma unroll
        for (int nt = 0; nt < 4; ++nt) {
            int c0 = nt * 8 + q * 2;
            float alv0 = __ldg(&al[c0]), alv1 = __ldg(&al[c0 + 1]);
            float arv0 = __ldg(&ar[c0]), arv1 = __ldg(&ar[c0 + 1]);
            pel0 += d[nt][0] * alv0 + d[nt][1] * alv1;
            per0 += d[nt][0] * arv0 + d[nt][1] * arv1;
            pel1 += d[nt][2] * alv0 + d[nt][3] * alv1;
            per1 += d[nt][2] * arv0 + d[nt][3] * arv1;
        }
#pragma unroll
        for (int o = 1; o < 4; o <<= 1) {
            pel0 += __shfl_xor_sync(0xffffffffu, pel0, o);
            per0 += __shfl_xor_sync(0xffffffffu, per0, o);
            pel1 += __shfl_xor_sync(0xffffffffu, pel1, o);
            per1 += __shfl_xor_sync(0xffffffffu, per1, o);
        }
        if (q == 0) {
            if (r0 < NNODES) { g_el2[r0] = pel0; g_er2[r0] = per0; }
            if (r1 < NNODES) { g_el2[r1] = pel1; g_er2[r1] = per1; }
        }
    }
#pragma unroll
    for (int nt = 0; nt < 4; ++nt) {
        int c0 = nt * 8 + q * 2;
        if (r0 < NNODES)
            ((__half2*)g_h2)[(size_t)r0 * 16 + (c0 >> 1)] =
                __floats2half2_rn(d[nt][0], d[nt][1]);
        if (r1 < NNODES)
            ((__half2*)g_h2)[(size_t)r1 * 16 + (c0 >> 1)] =
                __floats2half2_rn(d[nt][2], d[nt][3]);
    }
}

// ---------------- AGG layer2: warp/node, precomputed weights ----------------
__global__ __launch_bounds__(256) void agg2_kernel(const float* __restrict__ b2,
                                                   float* __restrict__ out) {
    int n = (blockIdx.x * 256 + threadIdx.x) >> 5;
    if (n >= NNODES) return;
    int l = threadIdx.x & 31;
    int s0 = g_rowptr[n], s1 = g_rowptr[n + 1];
    float bv = b2[l];
    float val = bv;
    if (s1 > s0) {
        float sm = 0.f, acc = 0.f;
        int s = g_csrc[s0];
        for (int j = s0; j < s1; ++j) {
            int snext = (j + 1 < s1) ? g_csrc[j + 1] : 0;
            float wg = __ldg(&g_w2e[j]);
            float f = __half2float(g_h2[(size_t)s * 32 + l]);
            sm += wg;
            acc = fmaf(wg, f, acc);
            s = snext;
        }
        val = acc / sm + bv;
    }
    out[(size_t)n * 32 + l] = val;
}

// ---------------- launch ----------------------------------------------------
extern "C" void kernel_launch(void* const* d_in, const int* in_sizes, int n_in,
                              void* d_out, int out_size) {
    const float* x   = (const float*)d_in[0];
    const int*   src = (const int*)d_in[1];
    const int*   dst = (const int*)d_in[2];
    const float* W1  = (const float*)d_in[3];
    const float* al1 = (const float*)d_in[4];
    const float* ar1 = (const float*)d_in[5];
    const float* b1  = (const float*)d_in[6];
    const float* W2  = (const float*)d_in[7];
    const float* al2 = (const float*)d_in[8];
    const float* ar2 = (const float*)d_in[9];
    const float* b2  = (const float*)d_in[10];
    float* out = (float*)d_out;

    setup_kernel<<<64, 256>>>(W1, W2);
    gemm1_kernel<<<(NNODES + GM_ROWS - 1) / GM_ROWS, 256>>>(x, al1, ar1);
    csr_kernel<<<CSR_BLOCKS, 1024>>>(src, dst);
    agg1_kernel<<<(NNODES * 32 + 255) / 256, 256>>>(b1);   // launch idx 3: profiled
    gemm2_kernel<<<(NNODES + GM_ROWS - 1) / GM_ROWS, 256>>>(al2, ar2);
    w2e_kernel<<<(NEDGES + 255) / 256, 256>>>();
    agg2_kernel<<<(NNODES * 32 + 255) / 256, 256>>>(b2, out);
}